// round 13
// baseline (speedup 1.0000x reference)
#include <cuda_runtime.h>
#include <cstdint>

// sMPS transfer-matrix contraction.
// N=2048, L=64, CHI=64, D=2, MIU2=4.
// E'(n) = sum_m T_m^T E(n) T_m;  E symmetric -> read E[r][d] as E[d][r].
// One CTA = 2 batch elements packed as float2 lanes; math is fma.rn.f32x2.
// R6: 8x4 tiles, 128 thr/CTA. R9: unroll-8 + 2-stage build. R12: depth-1 pipe.
// R13: period-3 software pipeline (3 operand sets, load-ahead ~2.5 k-steps)
//      to cover queue-inflated LDS latency (crossbar at 77%).

typedef unsigned long long u64;

#define PITCH 64
#define NTOT  2048

__device__ __forceinline__ u64 fma2(u64 a, u64 b, u64 c) {
    u64 d;
    asm("fma.rn.f32x2 %0, %1, %2, %3;" : "=l"(d) : "l"(a), "l"(b), "l"(c));
    return d;
}

// one operand set: 4 a-vectors (16B each) + 2 b-vectors
struct OpSet {
    ulonglong2 a0, a1, a2, a3, b0, b1;
};

__device__ __forceinline__ void ld_ops(OpSet& o, const float2* pe, const float2* pt) {
    o.a0 = *reinterpret_cast<const ulonglong2*>(pe);
    o.a1 = *reinterpret_cast<const ulonglong2*>(pe + 2);
    o.a2 = *reinterpret_cast<const ulonglong2*>(pe + 32);
    o.a3 = *reinterpret_cast<const ulonglong2*>(pe + 34);
    o.b0 = *reinterpret_cast<const ulonglong2*>(pt);
    o.b1 = *reinterpret_cast<const ulonglong2*>(pt + 32);
}

__device__ __forceinline__ void fma_ops(u64 acc[8][4], const OpSet& o) {
    u64 av[8] = {o.a0.x, o.a0.y, o.a1.x, o.a1.y, o.a2.x, o.a2.y, o.a3.x, o.a3.y};
    u64 bv[4] = {o.b0.x, o.b0.y, o.b1.x, o.b1.y};
    #pragma unroll
    for (int i = 0; i < 8; i++)
        #pragma unroll
        for (int j = 0; j < 4; j++)
            acc[i][j] = fma2(av[i], bv[j], acc[i][j]);
}

__global__ void __launch_bounds__(128, 2)
smps_kernel(const float* __restrict__ x,
            const float* __restrict__ mps0,
            const float* __restrict__ mpsm,
            const float* __restrict__ mpsl,
            float* __restrict__ out)
{
    extern __shared__ float2 sm[];
    float2* Es = sm;                   // 64 x PITCH : E state
    float2* Ts = Es + 64 * PITCH;      // 64 x PITCH : T_m scratch / t0 / v
    float2* Fs = Ts + 64 * PITCH;      // 64 x PITCH : F = E*T scratch
    float2* xs = Fs + 64 * PITCH;      // 128        : x rows (also tail-guard)

    const int tid = threadIdx.x;       // 0..127
    const int n0  = blockIdx.x * 2;
    const int ri  = tid >> 4;          // 0..7   (row-tile)
    const int ci  = tid & 15;          // 0..15  (col-tile)
    const int rA  = 4 * ri;            // rows rA..rA+3, rA+32..rA+35
    const int cA  = 2 * ci;            // cols cA,cA+1, cA+32,cA+33
    int R[8];
    #pragma unroll
    for (int i = 0; i < 4; i++) { R[i] = rA + i; R[4 + i] = 32 + rA + i; }
    const int C[4] = { cA, cA + 1, 32 + cA, 32 + cA + 1 };

    // ---- preload x for both lanes (128 float2) ----
    xs[tid] = make_float2(x[(size_t)n0 * 128 + tid],
                          x[(size_t)(n0 + 1) * 128 + tid]);
    __syncthreads();

    // ---- initial site: t0[a][d], 256 entries ----
    #pragma unroll
    for (int e = 0; e < 2; ++e) {
        int idx = tid + 128 * e;
        int a = idx >> 6, d = idx & 63;
        float w0 = mps0[(a * 2 + 0) * 64 + d];
        float w1 = mps0[(a * 2 + 1) * 64 + d];
        float2 xc0 = xs[0], xc1 = xs[1];
        Ts[a * PITCH + d] = make_float2(w0 * xc0.x + w1 * xc1.x,
                                        w0 * xc0.y + w1 * xc1.y);
    }
    __syncthreads();

    // ---- E0[r][c] = sum_a t0[a][r] * t0[a][c] ----
    #pragma unroll
    for (int i = 0; i < 8; i++) {
        #pragma unroll
        for (int j = 0; j < 4; j++) {
            float2 acc = make_float2(0.f, 0.f);
            #pragma unroll
            for (int a = 0; a < 4; a++) {
                float2 u = Ts[a * PITCH + R[i]];
                float2 v = Ts[a * PITCH + C[j]];
                acc.x += u.x * v.x;
                acc.y += u.y * v.y;
            }
            Es[R[i] * PITCH + C[j]] = acc;
        }
    }
    __syncthreads();

    // ---- 62 mid layers ----
    for (int l = 1; l <= 62; ++l) {
        const float* Al = mpsm + (size_t)(l - 1) * 4 * 64 * 128;  // [m][b][c][d]
        const float2 xc0 = xs[2 * l];
        const float2 xc1 = xs[2 * l + 1];

        u64 eacc[8][4] = {};   // E' accumulator across m

        #pragma unroll 1
        for (int m = 0; m < 4; ++m) {
            // --- build T_m: stage 1 = batch all LDGs (MLP=32), stage 2 = FMA+STS ---
            {
                float2 Lb[8][4];
                {
                    const float* Ar = Al + (size_t)m * 64 * 128 + (size_t)ri * 128 + cA;
                    #pragma unroll
                    for (int e = 0; e < 8; ++e) {
                        Lb[e][0] = *reinterpret_cast<const float2*>(Ar);        // c=0, lo
                        Lb[e][1] = *reinterpret_cast<const float2*>(Ar + 64);   // c=1, lo
                        Lb[e][2] = *reinterpret_cast<const float2*>(Ar + 32);   // c=0, hi
                        Lb[e][3] = *reinterpret_cast<const float2*>(Ar + 96);   // c=1, hi
                        Ar += 8 * 128;
                    }
                }
                float2* Tw = &Ts[ri * PITCH + cA];
                #pragma unroll
                for (int e = 0; e < 8; ++e) {
                    float2 p0 = Lb[e][0], p1 = Lb[e][1], q0 = Lb[e][2], q1 = Lb[e][3];
                    float4 ta, tb;
                    ta.x = p0.x * xc0.x + p1.x * xc1.x;  ta.y = p0.x * xc0.y + p1.x * xc1.y;
                    ta.z = p0.y * xc0.x + p1.y * xc1.x;  ta.w = p0.y * xc0.y + p1.y * xc1.y;
                    tb.x = q0.x * xc0.x + q1.x * xc1.x;  tb.y = q0.x * xc0.y + q1.x * xc1.y;
                    tb.z = q0.y * xc0.x + q1.y * xc1.x;  tb.w = q0.y * xc0.y + q1.y * xc1.y;
                    *reinterpret_cast<float4*>(Tw)      = ta;
                    *reinterpret_cast<float4*>(Tw + 32) = tb;
                    Tw += 8 * PITCH;
                }
            }
            __syncthreads();

            // --- GEMM1: F[r][c] = sum_d E[r][d]*T[d][c]; period-3 pipeline ---
            u64 acc[8][4] = {};
            {
                const float2* pe = Es + rA;   // row d, cols rA.. (symmetric read)
                const float2* pt = Ts + cA;
                OpSet S0, S1, S2;
                ld_ops(S0, pe, pt);                      // d = 0
                ld_ops(S1, pe + PITCH, pt + PITCH);      // d = 1
                pe += 2 * PITCH; pt += 2 * PITCH;        // at d = 2
                #pragma unroll 1
                for (int it = 0; it < 21; ++it) {
                    ld_ops(S2, pe, pt);                              // d+2
                    fma_ops(acc, S0);                                // d
                    ld_ops(S0, pe + PITCH, pt + PITCH);              // d+3
                    fma_ops(acc, S1);                                // d+1
                    ld_ops(S1, pe + 2 * PITCH, pt + 2 * PITCH);      // d+4 (tail: row 64 guard)
                    fma_ops(acc, S2);                                // d+2
                    pe += 3 * PITCH; pt += 3 * PITCH;
                }
                fma_ops(acc, S0);                        // d = 63
            }
            #pragma unroll
            for (int i = 0; i < 8; i++) {
                *reinterpret_cast<ulonglong2*>(&Fs[R[i] * PITCH + cA]) =
                    make_ulonglong2(acc[i][0], acc[i][1]);
                *reinterpret_cast<ulonglong2*>(&Fs[R[i] * PITCH + cA + 32]) =
                    make_ulonglong2(acc[i][2], acc[i][3]);
            }
            __syncthreads();

            // --- GEMM2: E'[f][g] += sum_b T[b][f]*F[b][g]; period-3 pipeline ---
            {
                const float2* pt = Ts + rA;
                const float2* pf = Fs + cA;
                OpSet S0, S1, S2;
                ld_ops(S0, pt, pf);                      // b = 0
                ld_ops(S1, pt + PITCH, pf + PITCH);      // b = 1
                pt += 2 * PITCH; pf += 2 * PITCH;        // at b = 2
                #pragma unroll 1
                for (int it = 0; it < 21; ++it) {
                    ld_ops(S2, pt, pf);                              // b+2
                    fma_ops(eacc, S0);                               // b
                    ld_ops(S0, pt + PITCH, pf + PITCH);              // b+3
                    fma_ops(eacc, S1);                               // b+1
                    ld_ops(S1, pt + 2 * PITCH, pf + 2 * PITCH);      // b+4 (tail: xs guard)
                    fma_ops(eacc, S2);                               // b+2
                    pt += 3 * PITCH; pf += 3 * PITCH;
                }
                fma_ops(eacc, S0);                       // b = 63
            }
            if (m < 3) {
                __syncthreads();   // protects Ts (next build) vs GEMM2 readers
            }
        }

        // --- write E' back into Es (Es readers finished at GEMM1(m=3) barrier) ---
        #pragma unroll
        for (int i = 0; i < 8; i++) {
            *reinterpret_cast<ulonglong2*>(&Es[R[i] * PITCH + cA]) =
                make_ulonglong2(eacc[i][0], eacc[i][1]);
            *reinterpret_cast<ulonglong2*>(&Es[R[i] * PITCH + cA + 32]) =
                make_ulonglong2(eacc[i][2], eacc[i][3]);
        }
        __syncthreads();           // Es/Ts ready for next layer
    }

    // ---- last site: v[m][b], 256 entries ----
    #pragma unroll
    for (int e = 0; e < 2; ++e) {
        int idx = tid + 128 * e;
        int m = idx >> 6, b = idx & 63;
        float w0 = mpsl[(m * 64 + b) * 2 + 0];
        float w1 = mpsl[(m * 64 + b) * 2 + 1];
        float2 xc0 = xs[2 * 63], xc1 = xs[2 * 63 + 1];
        Ts[m * PITCH + b] = make_float2(w0 * xc0.x + w1 * xc1.x,
                                        w0 * xc0.y + w1 * xc1.y);
    }
    __syncthreads();

    // ---- p = |sum_m v_m^T E v_m|: thread handles (m = tid>>5, d in {d0, 32+d0}) ----
    float2 part;
    {
        int m  = tid >> 5;         // 0..3
        int d0 = tid & 31;
        float2 u0 = make_float2(0.f, 0.f), u1 = make_float2(0.f, 0.f);
        #pragma unroll 4
        for (int b = 0; b < 64; ++b) {
            float2 v  = Ts[m * PITCH + b];
            float2 e0 = Es[b * PITCH + d0];
            float2 e1 = Es[b * PITCH + 32 + d0];
            u0.x += v.x * e0.x;  u0.y += v.y * e0.y;
            u1.x += v.x * e1.x;  u1.y += v.y * e1.y;
        }
        float2 v0 = Ts[m * PITCH + d0];
        float2 v1 = Ts[m * PITCH + 32 + d0];
        part = make_float2(u0.x * v0.x + u1.x * v1.x,
                           u0.y * v0.y + u1.y * v1.y);
    }
    #pragma unroll
    for (int off = 16; off > 0; off >>= 1) {
        part.x += __shfl_down_sync(0xffffffffu, part.x, off);
        part.y += __shfl_down_sync(0xffffffffu, part.y, off);
    }
    __syncthreads();           // Fs reuse as reduction scratch
    if ((tid & 31) == 0) Fs[tid >> 5] = part;
    __syncthreads();
    if (tid == 0) {
        float2 s = make_float2(0.f, 0.f);
        #pragma unroll
        for (int w = 0; w < 4; ++w) { s.x += Fs[w].x; s.y += Fs[w].y; }
        out[n0]     = fabsf(s.x);
        out[n0 + 1] = fabsf(s.y);
    }
}

extern "C" void kernel_launch(void* const* d_in, const int* in_sizes, int n_in,
                              void* d_out, int out_size)
{
    const float* x    = (const float*)d_in[0];   // (2048, 64, 2)
    const float* mps0 = (const float*)d_in[1];   // (4, 1, 2, 64)
    const float* mpsm = (const float*)d_in[2];   // (62, 4, 64, 2, 64)
    const float* mpsl = (const float*)d_in[3];   // (4, 64, 2, 1)
    float* out = (float*)d_out;                  // (2048, 1)

    size_t smem = (size_t)3 * 64 * PITCH * sizeof(float2) + 128 * sizeof(float2);
    cudaFuncSetAttribute(smps_kernel, cudaFuncAttributeMaxDynamicSharedMemorySize, (int)smem);
    smps_kernel<<<NTOT / 2, 128, smem>>>(x, mps0, mpsm, mpsl, out);
}

// round 14
// speedup vs baseline: 1.0309x; 1.0309x over previous
#include <cuda_runtime.h>
#include <cstdint>

// sMPS transfer-matrix contraction.
// N=2048, L=64, CHI=64, D=2, MIU2=4.
// E'(n) = sum_m T_m^T E(n) T_m;  E symmetric -> read E[r][d] as E[d][r].
// One CTA = 2 batch elements packed as float2 lanes; math is fma.rn.f32x2.
// R6: 8x4 tiles, 128 thr/CTA. R9: unroll-8 + 2-stage build.
// R12 (best 10424us): depth-1 software pipeline, fully unrolled.
// R13 period-3 rolled pipeline regressed -> reverted.
// R14: R12 with unroll 8 on the pair-loops (16 k-steps/body) for a longer
//      straight-line scheduling window.

typedef unsigned long long u64;

#define PITCH 64
#define NTOT  2048

__device__ __forceinline__ u64 fma2(u64 a, u64 b, u64 c) {
    u64 d;
    asm("fma.rn.f32x2 %0, %1, %2, %3;" : "=l"(d) : "l"(a), "l"(b), "l"(c));
    return d;
}

// one operand set: 4 a-vectors (16B each) + 2 b-vectors
struct OpSet {
    ulonglong2 a0, a1, a2, a3, b0, b1;
};

__device__ __forceinline__ void ld_ops(OpSet& o, const float2* pe, const float2* pt) {
    o.a0 = *reinterpret_cast<const ulonglong2*>(pe);
    o.a1 = *reinterpret_cast<const ulonglong2*>(pe + 2);
    o.a2 = *reinterpret_cast<const ulonglong2*>(pe + 32);
    o.a3 = *reinterpret_cast<const ulonglong2*>(pe + 34);
    o.b0 = *reinterpret_cast<const ulonglong2*>(pt);
    o.b1 = *reinterpret_cast<const ulonglong2*>(pt + 32);
}

__device__ __forceinline__ void fma_ops(u64 acc[8][4], const OpSet& o) {
    u64 av[8] = {o.a0.x, o.a0.y, o.a1.x, o.a1.y, o.a2.x, o.a2.y, o.a3.x, o.a3.y};
    u64 bv[4] = {o.b0.x, o.b0.y, o.b1.x, o.b1.y};
    #pragma unroll
    for (int i = 0; i < 8; i++)
        #pragma unroll
        for (int j = 0; j < 4; j++)
            acc[i][j] = fma2(av[i], bv[j], acc[i][j]);
}

__global__ void __launch_bounds__(128, 2)
smps_kernel(const float* __restrict__ x,
            const float* __restrict__ mps0,
            const float* __restrict__ mpsm,
            const float* __restrict__ mpsl,
            float* __restrict__ out)
{
    extern __shared__ float2 sm[];
    float2* Es = sm;                   // 64 x PITCH : E state
    float2* Ts = Es + 64 * PITCH;      // 64 x PITCH : T_m scratch / t0 / v
    float2* Fs = Ts + 64 * PITCH;      // 64 x PITCH : F = E*T scratch
    float2* xs = Fs + 64 * PITCH;      // 128        : x rows (also tail-guard)

    const int tid = threadIdx.x;       // 0..127
    const int n0  = blockIdx.x * 2;
    const int ri  = tid >> 4;          // 0..7   (row-tile)
    const int ci  = tid & 15;          // 0..15  (col-tile)
    const int rA  = 4 * ri;            // rows rA..rA+3, rA+32..rA+35
    const int cA  = 2 * ci;            // cols cA,cA+1, cA+32,cA+33
    int R[8];
    #pragma unroll
    for (int i = 0; i < 4; i++) { R[i] = rA + i; R[4 + i] = 32 + rA + i; }
    const int C[4] = { cA, cA + 1, 32 + cA, 32 + cA + 1 };

    // ---- preload x for both lanes (128 float2) ----
    xs[tid] = make_float2(x[(size_t)n0 * 128 + tid],
                          x[(size_t)(n0 + 1) * 128 + tid]);
    __syncthreads();

    // ---- initial site: t0[a][d], 256 entries ----
    #pragma unroll
    for (int e = 0; e < 2; ++e) {
        int idx = tid + 128 * e;
        int a = idx >> 6, d = idx & 63;
        float w0 = mps0[(a * 2 + 0) * 64 + d];
        float w1 = mps0[(a * 2 + 1) * 64 + d];
        float2 xc0 = xs[0], xc1 = xs[1];
        Ts[a * PITCH + d] = make_float2(w0 * xc0.x + w1 * xc1.x,
                                        w0 * xc0.y + w1 * xc1.y);
    }
    __syncthreads();

    // ---- E0[r][c] = sum_a t0[a][r] * t0[a][c] ----
    #pragma unroll
    for (int i = 0; i < 8; i++) {
        #pragma unroll
        for (int j = 0; j < 4; j++) {
            float2 acc = make_float2(0.f, 0.f);
            #pragma unroll
            for (int a = 0; a < 4; a++) {
                float2 u = Ts[a * PITCH + R[i]];
                float2 v = Ts[a * PITCH + C[j]];
                acc.x += u.x * v.x;
                acc.y += u.y * v.y;
            }
            Es[R[i] * PITCH + C[j]] = acc;
        }
    }
    __syncthreads();

    // ---- 62 mid layers ----
    for (int l = 1; l <= 62; ++l) {
        const float* Al = mpsm + (size_t)(l - 1) * 4 * 64 * 128;  // [m][b][c][d]
        const float2 xc0 = xs[2 * l];
        const float2 xc1 = xs[2 * l + 1];

        u64 eacc[8][4] = {};   // E' accumulator across m

        #pragma unroll 1
        for (int m = 0; m < 4; ++m) {
            // --- build T_m: stage 1 = batch all LDGs (MLP=32), stage 2 = FMA+STS ---
            {
                float2 Lb[8][4];
                {
                    const float* Ar = Al + (size_t)m * 64 * 128 + (size_t)ri * 128 + cA;
                    #pragma unroll
                    for (int e = 0; e < 8; ++e) {
                        Lb[e][0] = *reinterpret_cast<const float2*>(Ar);        // c=0, lo
                        Lb[e][1] = *reinterpret_cast<const float2*>(Ar + 64);   // c=1, lo
                        Lb[e][2] = *reinterpret_cast<const float2*>(Ar + 32);   // c=0, hi
                        Lb[e][3] = *reinterpret_cast<const float2*>(Ar + 96);   // c=1, hi
                        Ar += 8 * 128;
                    }
                }
                float2* Tw = &Ts[ri * PITCH + cA];
                #pragma unroll
                for (int e = 0; e < 8; ++e) {
                    float2 p0 = Lb[e][0], p1 = Lb[e][1], q0 = Lb[e][2], q1 = Lb[e][3];
                    float4 ta, tb;
                    ta.x = p0.x * xc0.x + p1.x * xc1.x;  ta.y = p0.x * xc0.y + p1.x * xc1.y;
                    ta.z = p0.y * xc0.x + p1.y * xc1.x;  ta.w = p0.y * xc0.y + p1.y * xc1.y;
                    tb.x = q0.x * xc0.x + q1.x * xc1.x;  tb.y = q0.x * xc0.y + q1.x * xc1.y;
                    tb.z = q0.y * xc0.x + q1.y * xc1.x;  tb.w = q0.y * xc0.y + q1.y * xc1.y;
                    *reinterpret_cast<float4*>(Tw)      = ta;
                    *reinterpret_cast<float4*>(Tw + 32) = tb;
                    Tw += 8 * PITCH;
                }
            }
            __syncthreads();

            // --- GEMM1: F[r][c] = sum_d E[r][d]*T[d][c]; software-pipelined ---
            u64 acc[8][4] = {};
            {
                const float2* pe = Es + rA;   // row d, cols rA.. (symmetric read)
                const float2* pt = Ts + cA;
                OpSet A, B;
                ld_ops(A, pe, pt);            // d = 0
                #pragma unroll 8
                for (int d = 0; d < 64; d += 2) {
                    ld_ops(B, pe + PITCH, pt + PITCH);        // d+1
                    fma_ops(acc, A);                          // d
                    pe += 2 * PITCH; pt += 2 * PITCH;
                    ld_ops(A, pe, pt);                        // d+2 (tail: row 64 = next buffer, unused)
                    fma_ops(acc, B);                          // d+1
                }
            }
            #pragma unroll
            for (int i = 0; i < 8; i++) {
                *reinterpret_cast<ulonglong2*>(&Fs[R[i] * PITCH + cA]) =
                    make_ulonglong2(acc[i][0], acc[i][1]);
                *reinterpret_cast<ulonglong2*>(&Fs[R[i] * PITCH + cA + 32]) =
                    make_ulonglong2(acc[i][2], acc[i][3]);
            }
            __syncthreads();

            // --- GEMM2: E'[f][g] += sum_b T[b][f]*F[b][g]; software-pipelined ---
            {
                const float2* pt = Ts + rA;
                const float2* pf = Fs + cA;
                OpSet A, B;
                ld_ops(A, pt, pf);            // b = 0
                #pragma unroll 8
                for (int b = 0; b < 64; b += 2) {
                    ld_ops(B, pt + PITCH, pf + PITCH);        // b+1
                    fma_ops(eacc, A);                         // b
                    pt += 2 * PITCH; pf += 2 * PITCH;
                    ld_ops(A, pt, pf);                        // b+2 (tail reads xs region, unused)
                    fma_ops(eacc, B);                         // b+1
                }
            }
            if (m < 3) {
                __syncthreads();   // protects Ts (next build) vs GEMM2 readers
            }
        }

        // --- write E' back into Es (Es readers finished at GEMM1(m=3) barrier) ---
        #pragma unroll
        for (int i = 0; i < 8; i++) {
            *reinterpret_cast<ulonglong2*>(&Es[R[i] * PITCH + cA]) =
                make_ulonglong2(eacc[i][0], eacc[i][1]);
            *reinterpret_cast<ulonglong2*>(&Es[R[i] * PITCH + cA + 32]) =
                make_ulonglong2(eacc[i][2], eacc[i][3]);
        }
        __syncthreads();           // Es/Ts ready for next layer
    }

    // ---- last site: v[m][b], 256 entries ----
    #pragma unroll
    for (int e = 0; e < 2; ++e) {
        int idx = tid + 128 * e;
        int m = idx >> 6, b = idx & 63;
        float w0 = mpsl[(m * 64 + b) * 2 + 0];
        float w1 = mpsl[(m * 64 + b) * 2 + 1];
        float2 xc0 = xs[2 * 63], xc1 = xs[2 * 63 + 1];
        Ts[m * PITCH + b] = make_float2(w0 * xc0.x + w1 * xc1.x,
                                        w0 * xc0.y + w1 * xc1.y);
    }
    __syncthreads();

    // ---- p = |sum_m v_m^T E v_m|: thread handles (m = tid>>5, d in {d0, 32+d0}) ----
    float2 part;
    {
        int m  = tid >> 5;         // 0..3
        int d0 = tid & 31;
        float2 u0 = make_float2(0.f, 0.f), u1 = make_float2(0.f, 0.f);
        #pragma unroll 4
        for (int b = 0; b < 64; ++b) {
            float2 v  = Ts[m * PITCH + b];
            float2 e0 = Es[b * PITCH + d0];
            float2 e1 = Es[b * PITCH + 32 + d0];
            u0.x += v.x * e0.x;  u0.y += v.y * e0.y;
            u1.x += v.x * e1.x;  u1.y += v.y * e1.y;
        }
        float2 v0 = Ts[m * PITCH + d0];
        float2 v1 = Ts[m * PITCH + 32 + d0];
        part = make_float2(u0.x * v0.x + u1.x * v1.x,
                           u0.y * v0.y + u1.y * v1.y);
    }
    #pragma unroll
    for (int off = 16; off > 0; off >>= 1) {
        part.x += __shfl_down_sync(0xffffffffu, part.x, off);
        part.y += __shfl_down_sync(0xffffffffu, part.y, off);
    }
    __syncthreads();           // Fs reuse as reduction scratch
    if ((tid & 31) == 0) Fs[tid >> 5] = part;
    __syncthreads();
    if (tid == 0) {
        float2 s = make_float2(0.f, 0.f);
        #pragma unroll
        for (int w = 0; w < 4; ++w) { s.x += Fs[w].x; s.y += Fs[w].y; }
        out[n0]     = fabsf(s.x);
        out[n0 + 1] = fabsf(s.y);
    }
}

extern "C" void kernel_launch(void* const* d_in, const int* in_sizes, int n_in,
                              void* d_out, int out_size)
{
    const float* x    = (const float*)d_in[0];   // (2048, 64, 2)
    const float* mps0 = (const float*)d_in[1];   // (4, 1, 2, 64)
    const float* mpsm = (const float*)d_in[2];   // (62, 4, 64, 2, 64)
    const float* mpsl = (const float*)d_in[3];   // (4, 64, 2, 1)
    float* out = (float*)d_out;                  // (2048, 1)

    size_t smem = (size_t)3 * 64 * PITCH * sizeof(float2) + 128 * sizeof(float2);
    cudaFuncSetAttribute(smps_kernel, cudaFuncAttributeMaxDynamicSharedMemorySize, (int)smem);
    smps_kernel<<<NTOT / 2, 128, smem>>>(x, mps0, mpsm, mpsl, out);
}